// round 16
// baseline (speedup 1.0000x reference)
#include <cuda_runtime.h>

#define T_DIM 512
#define B_DIM 256
#define D_DIM 128
#define H_DIM 128
#define Q_DIM 8

#define N_FULL 108   // CTAs carrying 2 batch elements (108*2 + 40*1 = 256)
#define N_GRID 148   // one CTA per SM

// MUFU.TANH-based activations (sm_75+): ~2^-11 abs err, one MUFU each.
__device__ __forceinline__ float tanh_approx(float x) {
    float r;
    asm("tanh.approx.f32 %0, %1;" : "=f"(r) : "f"(x));
    return r;
}
__device__ __forceinline__ float fsig(float x) {          // sigmoid
    return fmaf(tanh_approx(0.5f * x), 0.5f, 0.5f);
}

// 148 CTAs x 128 threads; each CTA runs 1-2 batch elements' full T=512
// recurrence with the two elements' chains interleaved per-thread (ILP).
// Weights shared between the pair: W in registers (16 float4), U in registers.
// Single-element CTAs run a branch-free dummy twin (never stored).
__global__ __launch_bounds__(128) void qlstm_scan_kernel(
    const float* __restrict__ x,     // (T,B,D)
    const float* __restrict__ Wf, const float* __restrict__ bf,
    const float* __restrict__ thf, const float* __restrict__ Uf, const float* __restrict__ cf,
    const float* __restrict__ Wi, const float* __restrict__ bi,
    const float* __restrict__ thi, const float* __restrict__ Ui, const float* __restrict__ ci,
    const float* __restrict__ Wg, const float* __restrict__ bg,
    const float* __restrict__ thg, const float* __restrict__ Ug, const float* __restrict__ cg,
    const float* __restrict__ Wo, const float* __restrict__ bo,
    const float* __restrict__ tho, const float* __restrict__ Uo, const float* __restrict__ co,
    float* __restrict__ out)         // outs (T,B,H) ++ hx (B,H) ++ cx (B,H)
{
    __shared__ float comb0[256];     // elem 0: [0:128)=x_t, [128:256)=h_t
    __shared__ float comb1[256];     // elem 1
    __shared__ float4 ct0[8];        // elem 0 cos table (32 floats)
    __shared__ float4 ct1[8];        // elem 1 cos table

    const int tid  = threadIdx.x;
    const int cta  = blockIdx.x;
    const int o    = tid >> 2;       // 0..31: this thread's z-output (g*8+q)
    const int part = tid & 3;        // quarter of the 256-dot
    const int g_o  = o >> 3;
    const int q_o  = o & 7;

    // batch mapping: cta<108 -> {2c, 2c+1}; else single {216 + (c-108)}
    const bool two = (cta < N_FULL);
    const int b0 = two ? (cta * 2) : (N_FULL * 2 + (cta - N_FULL));
    const int b1 = two ? (b0 + 1) : b0;   // dummy twin aliases b0 (reads only)

    // ---- W into registers (invariant, shared by both elements) ----
    float4 Wreg[16];
    {
        const float* wsrc = (o < 16) ? ((o < 8) ? Wf : Wi) : ((o < 24) ? Wg : Wo);
        const float4* wrow = (const float4*)(wsrc + (o & 7) * 256);
#pragma unroll
        for (int j = 0; j < 16; ++j)
            Wreg[j] = wrow[4 * j + part];
    }

    const float bias_th =
        ((g_o == 0) ? bf : (g_o == 1) ? bi : (g_o == 2) ? bg : bo)[q_o] +
        ((g_o == 0) ? thf : (g_o == 1) ? thi : (g_o == 2) ? thg : tho)[q_o];

    // U in registers: thread t owns hidden index hh = tid (both elements)
    float Ur[4][8];
    float cbr[4];
    {
        const float* Us[4] = {Uf, Ui, Ug, Uo};
        const float* cs[4] = {cf, ci, cg, co};
#pragma unroll
        for (int g = 0; g < 4; ++g) {
            const float4 u0 = ((const float4*)(Us[g] + tid * 8))[0];
            const float4 u1 = ((const float4*)(Us[g] + tid * 8))[1];
            Ur[g][0] = u0.x; Ur[g][1] = u0.y; Ur[g][2] = u0.z; Ur[g][3] = u0.w;
            Ur[g][4] = u1.x; Ur[g][5] = u1.y; Ur[g][6] = u1.z; Ur[g][7] = u1.w;
            cbr[g] = cs[g][tid];
        }
    }

    // ---- per-element state + running pointers ----
    const int XS = B_DIM * D_DIM;    // x step stride (floats)
    comb0[tid]       = x[b0 * D_DIM + tid];
    comb0[128 + tid] = 0.f;
    comb1[tid]       = x[b1 * D_DIM + tid];
    comb1[128 + tid] = 0.f;
    float creg0 = 0.f, creg1 = 0.f;
    float xcur0 = x[(size_t)XS + b0 * D_DIM + tid];
    float xcur1 = x[(size_t)XS + b1 * D_DIM + tid];
    const float* xptr0 = x + (size_t)2 * XS + b0 * D_DIM + tid;
    const float* xptr1 = x + (size_t)2 * XS + b1 * D_DIM + tid;
    float* optr0 = out + b0 * H_DIM + tid;
    float* optr1 = out + b1 * H_DIM + tid;
    float hlast0 = 0.f, hlast1 = 0.f;
    __syncthreads();

    const unsigned FULL = 0xffffffffu;
    float* ctf0 = (float*)ct0;
    float* ctf1 = (float*)ct1;

    for (int step = 0; step < T_DIM; ++step) {
        // ---- dots for both elements, interleaved (shared W operands) ----
        const float4* c40 = (const float4*)comb0;
        const float4* c41 = (const float4*)comb1;
        float ax0 = 0.f, ay0 = 0.f, az0 = 0.f, aw0 = 0.f;
        float ax1 = 0.f, ay1 = 0.f, az1 = 0.f, aw1 = 0.f;
#pragma unroll
        for (int j = 0; j < 16; ++j) {
            const float4 w  = Wreg[j];
            const float4 v0 = c40[4 * j + part];
            const float4 v1 = c41[4 * j + part];
            ax0 += v0.x * w.x; ay0 += v0.y * w.y;
            az0 += v0.z * w.z; aw0 += v0.w * w.w;
            ax1 += v1.x * w.x; ay1 += v1.y * w.y;
            az1 += v1.z * w.z; aw1 += v1.w * w.w;
        }
        float z0 = (ax0 + ay0) + (az0 + aw0);
        float z1 = (ax1 + ay1) + (az1 + aw1);
        z0 += __shfl_xor_sync(FULL, z0, 1);
        z1 += __shfl_xor_sync(FULL, z1, 1);
        z0 += __shfl_xor_sync(FULL, z0, 2);
        z1 += __shfl_xor_sync(FULL, z1, 2);
        if (part == 0) {
            ctf0[o] = __cosf(z0 + bias_th);
            ctf1[o] = __cosf(z1 + bias_th);
        }
        __syncthreads();  // cos tables published; all comb reads done

        // stage x_{t+1} (dead region post-sync) + prefetch x_{t+2}
        comb0[tid] = xcur0;
        comb1[tid] = xcur1;
        if (step + 2 < T_DIM) {
            xcur0 = *xptr0; xptr0 += XS;
            xcur1 = *xptr1; xptr1 += XS;
        }

        // ---- prefix/suffix products + U projection, both elements ----
        float acc0[4], acc1[4];
#pragma unroll
        for (int g = 0; g < 4; ++g) {
            {
                const float4 cA = ct0[g * 2];
                const float4 cB = ct0[g * 2 + 1];
                const float s67 = cB.z * cB.w;
                const float s47 = cB.x * cB.y * s67;
                const float e0  = cA.y * cA.z * cA.w * s47;
                const float cp1 = cA.x * cA.y;
                const float cp2 = cp1 * cA.z;
                const float cp3 = cp2 * cA.w;
                const float cp4 = cp3 * cB.x;
                const float cp5 = cp4 * cB.y;
                const float cp6 = cp5 * cB.z;
                const float cp7 = cp6 * cB.w;
                float a = cbr[g];
                a += e0  * Ur[g][0];
                a += cp1 * Ur[g][1];
                a += cp2 * Ur[g][2];
                a += cp3 * Ur[g][3];
                a += cp4 * Ur[g][4];
                a += cp5 * Ur[g][5];
                a += cp6 * Ur[g][6];
                a += cp7 * Ur[g][7];
                acc0[g] = a;
            }
            {
                const float4 cA = ct1[g * 2];
                const float4 cB = ct1[g * 2 + 1];
                const float s67 = cB.z * cB.w;
                const float s47 = cB.x * cB.y * s67;
                const float e0  = cA.y * cA.z * cA.w * s47;
                const float cp1 = cA.x * cA.y;
                const float cp2 = cp1 * cA.z;
                const float cp3 = cp2 * cA.w;
                const float cp4 = cp3 * cB.x;
                const float cp5 = cp4 * cB.y;
                const float cp6 = cp5 * cB.z;
                const float cp7 = cp6 * cB.w;
                float a = cbr[g];
                a += e0  * Ur[g][0];
                a += cp1 * Ur[g][1];
                a += cp2 * Ur[g][2];
                a += cp3 * Ur[g][3];
                a += cp4 * Ur[g][4];
                a += cp5 * Ur[g][5];
                a += cp6 * Ur[g][6];
                a += cp7 * Ur[g][7];
                acc1[g] = a;
            }
        }

        // ---- cell updates ----
        const float fv0 = fsig(acc0[0]);
        const float iv0 = fsig(acc0[1]);
        const float gv0 = tanh_approx(acc0[2]);
        const float ov0 = fsig(acc0[3]);
        creg0 = fv0 * creg0 + iv0 * gv0;
        const float hv0 = ov0 * tanh_approx(creg0);

        const float fv1 = fsig(acc1[0]);
        const float iv1 = fsig(acc1[1]);
        const float gv1 = tanh_approx(acc1[2]);
        const float ov1 = fsig(acc1[3]);
        creg1 = fv1 * creg1 + iv1 * gv1;
        const float hv1 = ov1 * tanh_approx(creg1);

        comb0[128 + tid] = hv0;
        comb1[128 + tid] = hv1;
        *optr0 = hv0;
        optr0 += B_DIM * H_DIM;
        if (two) {                       // predicated store; dummy twin never lands
            *optr1 = hv1;
        }
        optr1 += B_DIM * H_DIM;
        hlast0 = hv0; hlast1 = hv1;
        __syncthreads();  // h (and staged x) published for next step
    }

    // finals: hx then cx
    const size_t base = (size_t)T_DIM * B_DIM * H_DIM;
    out[base + b0 * H_DIM + tid] = hlast0;
    out[base + (size_t)B_DIM * H_DIM + b0 * H_DIM + tid] = creg0;
    if (two) {
        out[base + b1 * H_DIM + tid] = hlast1;
        out[base + (size_t)B_DIM * H_DIM + b1 * H_DIM + tid] = creg1;
    }
}

extern "C" void kernel_launch(void* const* d_in, const int* in_sizes, int n_in,
                              void* d_out, int out_size) {
    (void)in_sizes; (void)n_in; (void)out_size;
    const float* x   = (const float*)d_in[0];
    const float* Wf  = (const float*)d_in[1];
    const float* bf  = (const float*)d_in[2];
    const float* thf = (const float*)d_in[3];
    const float* Uf  = (const float*)d_in[4];
    const float* cf  = (const float*)d_in[5];
    const float* Wi  = (const float*)d_in[6];
    const float* bi  = (const float*)d_in[7];
    const float* thi = (const float*)d_in[8];
    const float* Ui  = (const float*)d_in[9];
    const float* ci  = (const float*)d_in[10];
    const float* Wg  = (const float*)d_in[11];
    const float* bg  = (const float*)d_in[12];
    const float* thg = (const float*)d_in[13];
    const float* Ug  = (const float*)d_in[14];
    const float* cg  = (const float*)d_in[15];
    const float* Wo  = (const float*)d_in[16];
    const float* bo  = (const float*)d_in[17];
    const float* tho = (const float*)d_in[18];
    const float* Uo  = (const float*)d_in[19];
    const float* co  = (const float*)d_in[20];
    float* out = (float*)d_out;

    qlstm_scan_kernel<<<N_GRID, 128>>>(
        x,
        Wf, bf, thf, Uf, cf,
        Wi, bi, thi, Ui, ci,
        Wg, bg, thg, Ug, cg,
        Wo, bo, tho, Uo, co,
        out);
}

// round 17
// speedup vs baseline: 1.8300x; 1.8300x over previous
#include <cuda_runtime.h>

#define T_DIM 512
#define B_DIM 256
#define D_DIM 128
#define H_DIM 128
#define Q_DIM 8

#define ZX_N 32                 // 4 gates x 8 qubits
#define TILE_R 32               // rows per prepass CTA
#define ROWS_PT 4               // rows per prepass thread

// zx scratch: [T+1][B][32]  (one extra step so the scan's prefetch never goes OOB)
__device__ float g_zx[(T_DIM + 1) * B_DIM * ZX_N];

// MUFU.TANH-based activations (sm_75+): ~2^-11 abs err, one MUFU each.
__device__ __forceinline__ float tanh_approx(float x) {
    float r;
    asm("tanh.approx.f32 %0, %1;" : "=f"(r) : "f"(x));
    return r;
}
__device__ __forceinline__ float fsig(float x) {          // sigmoid
    return fmaf(tanh_approx(0.5f * x), 0.5f, 0.5f);
}

// ---------------- prepass: ZX[t,b,o] = x[t,b,:] . Wx[o,:] + bias[o] + theta[o] ----
// x is (T,B,D) row-major -> flat rows r = t*B + b of length 128.
// grid = T*B/TILE_R CTAs, 256 threads: thread (o = tid&31, rg = tid>>5) computes
// ROWS_PT consecutive rows for its output o. x reads are warp-uniform (L1-hit),
// W reads are conflict-free LDS.128 (row stride 132 floats).
__global__ __launch_bounds__(256) void zx_kernel(
    const float* __restrict__ x,
    const float* __restrict__ Wf, const float* __restrict__ bf, const float* __restrict__ thf,
    const float* __restrict__ Wi, const float* __restrict__ bi, const float* __restrict__ thi,
    const float* __restrict__ Wg, const float* __restrict__ bg, const float* __restrict__ thg,
    const float* __restrict__ Wo, const float* __restrict__ bo, const float* __restrict__ tho)
{
    __shared__ float Ws[32][132];    // [o][0:128) = Wx row; [o][128] = bias+theta

    const int tid = threadIdx.x;
    const int o   = tid & 31;
    const int rg  = tid >> 5;

    for (int i = tid; i < 32 * 128; i += 256) {
        const int oo = i >> 7;
        const int e  = i & 127;
        const float* wsrc = (oo < 16) ? ((oo < 8) ? Wf : Wi) : ((oo < 24) ? Wg : Wo);
        Ws[oo][e] = wsrc[(oo & 7) * 256 + e];   // x-half of row (cols 0..127)
    }
    if (tid < 32) {
        const int gg = tid >> 3, qq = tid & 7;
        const float* bsrc  = (gg == 0) ? bf  : (gg == 1) ? bi  : (gg == 2) ? bg  : bo;
        const float* thsrc = (gg == 0) ? thf : (gg == 1) ? thi : (gg == 2) ? thg : tho;
        Ws[tid][128] = bsrc[qq] + thsrc[qq];
    }
    __syncthreads();

    const size_t r0 = (size_t)blockIdx.x * TILE_R + rg * ROWS_PT;
    const float4* x4 = (const float4*)(x + r0 * D_DIM);       // 4 rows x 32 float4
    const float4* w4 = (const float4*)&Ws[o][0];

    float acc[ROWS_PT] = {0.f, 0.f, 0.f, 0.f};
#pragma unroll
    for (int k = 0; k < 32; ++k) {
        const float4 w = w4[k];
#pragma unroll
        for (int i = 0; i < ROWS_PT; ++i) {
            const float4 xv = x4[i * 32 + k];
            acc[i] += xv.x * w.x + xv.y * w.y + xv.z * w.z + xv.w * w.w;
        }
    }
    const float bth = Ws[o][128];
#pragma unroll
    for (int i = 0; i < ROWS_PT; ++i)
        g_zx[(r0 + i) * ZX_N + o] = acc[i] + bth;
}

// ---------------- scan: one CTA per batch element, 128 threads ------------------
// Per step, per thread: 8 LDS.128 + 32 FFMA (h-half dot only), 2-shfl reduce,
// part0 does cos(z + zx) pre-barrier; zx prefetched one step ahead (off-chain).
__global__ __launch_bounds__(128) void qlstm_scan_kernel(
    const float* __restrict__ Wf, const float* __restrict__ Uf, const float* __restrict__ cf,
    const float* __restrict__ Wi, const float* __restrict__ Ui, const float* __restrict__ ci,
    const float* __restrict__ Wg, const float* __restrict__ Ug, const float* __restrict__ cg,
    const float* __restrict__ Wo, const float* __restrict__ Uo, const float* __restrict__ co,
    float* __restrict__ out)         // outs (T,B,H) ++ hx (B,H) ++ cx (B,H)
{
    __shared__ float comb[128];      // h_t
    __shared__ float4 ct4[8];        // cos table: cos(z+b+th) for 32 outputs

    const int tid  = threadIdx.x;
    const int b    = blockIdx.x;
    const int o    = tid >> 2;       // 0..31: this thread's z-output (g*8+q)
    const int part = tid & 3;        // quarter of the 128-dot

    // ---- Wh (h-half) into registers: 8 float4/thread ----
    float4 Wh[8];
    {
        const float* wsrc = (o < 16) ? ((o < 8) ? Wf : Wi) : ((o < 24) ? Wg : Wo);
        const float4* wrow = (const float4*)(wsrc + (o & 7) * 256);
#pragma unroll
        for (int j = 0; j < 8; ++j)
            Wh[j] = wrow[32 + 4 * j + part];   // cols 128..255
    }

    // U in registers: thread t permanently owns hidden index hh = tid
    float Ur[4][8];
    float cbr[4];
    {
        const float* Us[4] = {Uf, Ui, Ug, Uo};
        const float* cs[4] = {cf, ci, cg, co};
#pragma unroll
        for (int g = 0; g < 4; ++g) {
            const float4 u0 = ((const float4*)(Us[g] + tid * 8))[0];
            const float4 u1 = ((const float4*)(Us[g] + tid * 8))[1];
            Ur[g][0] = u0.x; Ur[g][1] = u0.y; Ur[g][2] = u0.z; Ur[g][3] = u0.w;
            Ur[g][4] = u1.x; Ur[g][5] = u1.y; Ur[g][6] = u1.z; Ur[g][7] = u1.w;
            cbr[g] = cs[g][tid];
        }
    }

    // zx pipeline: zxc = zx for current step; prefetch next at step top
    const float* zxp = g_zx + (size_t)b * ZX_N + o;   // [t=0][b][o]
    float zxc = *zxp;
    zxp += B_DIM * ZX_N;                              // -> t=1

    comb[tid] = 0.f;                 // h_0
    float creg  = 0.f;
    float* optr = out + b * H_DIM + tid;
    float hlast = 0.f;
    __syncthreads();

    const unsigned FULL = 0xffffffffu;
    float* ctable = (float*)ct4;

    for (int step = 0; step < T_DIM; ++step) {
        // prefetch zx for step+1 (buffer has a spare step, never OOB)
        const float zxn = *zxp;
        zxp += B_DIM * ZX_N;

        // ---- h-half dot: z[o] += h . Wh[o]  (4 threads per output) ----
        const float4* c4 = (const float4*)comb;
        float ax = 0.f, ay = 0.f, az = 0.f, aw = 0.f;
#pragma unroll
        for (int j = 0; j < 8; ++j) {
            const float4 cv = c4[4 * j + part];
            ax += cv.x * Wh[j].x; ay += cv.y * Wh[j].y;
            az += cv.z * Wh[j].z; aw += cv.w * Wh[j].w;
        }
        float z = (ax + ay) + (az + aw);
        z += __shfl_xor_sync(FULL, z, 1);
        z += __shfl_xor_sync(FULL, z, 2);
        if (part == 0) ctable[o] = __cosf(z + zxc);   // zx carries bias+theta
        __syncthreads();  // ctable published; all comb reads done

        // ---- prefix/suffix products from broadcast cos table + U projection ----
        float acc[4];
#pragma unroll
        for (int g = 0; g < 4; ++g) {
            const float4 cA = ct4[g * 2];
            const float4 cB = ct4[g * 2 + 1];
            const float s67 = cB.z * cB.w;
            const float s47 = cB.x * cB.y * s67;
            const float e0  = cA.y * cA.z * cA.w * s47;   // c1..c7
            const float cp1 = cA.x * cA.y;
            const float cp2 = cp1 * cA.z;
            const float cp3 = cp2 * cA.w;
            const float cp4 = cp3 * cB.x;
            const float cp5 = cp4 * cB.y;
            const float cp6 = cp5 * cB.z;
            const float cp7 = cp6 * cB.w;
            float a = cbr[g];
            a += e0  * Ur[g][0];
            a += cp1 * Ur[g][1];
            a += cp2 * Ur[g][2];
            a += cp3 * Ur[g][3];
            a += cp4 * Ur[g][4];
            a += cp5 * Ur[g][5];
            a += cp6 * Ur[g][6];
            a += cp7 * Ur[g][7];
            acc[g] = a;
        }

        // ---- cell update (MUFU.TANH activations) ----
        const float fv = fsig(acc[0]);
        const float iv = fsig(acc[1]);
        const float gv = tanh_approx(acc[2]);
        const float ov = fsig(acc[3]);
        creg = fv * creg + iv * gv;
        const float hv = ov * tanh_approx(creg);

        comb[tid] = hv;
        *optr = hv;
        optr += B_DIM * H_DIM;
        hlast = hv;
        zxc = zxn;
        __syncthreads();  // h published for next step
    }

    // finals: hx then cx
    const size_t base = (size_t)T_DIM * B_DIM * H_DIM;
    out[base + b * H_DIM + tid] = hlast;
    out[base + (size_t)B_DIM * H_DIM + b * H_DIM + tid] = creg;
}

extern "C" void kernel_launch(void* const* d_in, const int* in_sizes, int n_in,
                              void* d_out, int out_size) {
    (void)in_sizes; (void)n_in; (void)out_size;
    const float* x   = (const float*)d_in[0];
    const float* Wf  = (const float*)d_in[1];
    const float* bf  = (const float*)d_in[2];
    const float* thf = (const float*)d_in[3];
    const float* Uf  = (const float*)d_in[4];
    const float* cf  = (const float*)d_in[5];
    const float* Wi  = (const float*)d_in[6];
    const float* bi  = (const float*)d_in[7];
    const float* thi = (const float*)d_in[8];
    const float* Ui  = (const float*)d_in[9];
    const float* ci  = (const float*)d_in[10];
    const float* Wg  = (const float*)d_in[11];
    const float* bg  = (const float*)d_in[12];
    const float* thg = (const float*)d_in[13];
    const float* Ug  = (const float*)d_in[14];
    const float* cg  = (const float*)d_in[15];
    const float* Wo  = (const float*)d_in[16];
    const float* bo  = (const float*)d_in[17];
    const float* tho = (const float*)d_in[18];
    const float* Uo  = (const float*)d_in[19];
    const float* co  = (const float*)d_in[20];
    float* out = (float*)d_out;

    zx_kernel<<<T_DIM * B_DIM / TILE_R, 256>>>(
        x,
        Wf, bf, thf,
        Wi, bi, thi,
        Wg, bg, thg,
        Wo, bo, tho);

    qlstm_scan_kernel<<<B_DIM, 128>>>(
        Wf, Uf, cf,
        Wi, Ui, ci,
        Wg, Ug, cg,
        Wo, Uo, co,
        out);
}